// round 2
// baseline (speedup 1.0000x reference)
#include <cuda_runtime.h>
#include <math.h>

// Problem: B=64, T=512, V=50000, E=300, H1=256, H2=512, D1=128, D2=64, C=1
// Inputs (metadata order): tokens, emb, W1x, W1h, b1, W2x, W2h, b2,
//                          Wd1, bd1, Wd2, bd2, Wc, bc

typedef unsigned long long ull;

// ---------------- packed f32x2 helpers ----------------
__device__ __forceinline__ ull pack2(float lo, float hi) {
    ull r; asm("mov.b64 %0,{%1,%2};" : "=l"(r) : "f"(lo), "f"(hi)); return r;
}
__device__ __forceinline__ ull splat2(float v) { return pack2(v, v); }
__device__ __forceinline__ float2 unpack2(ull v) {
    float2 r; asm("mov.b64 {%0,%1},%2;" : "=f"(r.x), "=f"(r.y) : "l"(v)); return r;
}
__device__ __forceinline__ ull fma2(ull a, ull b, ull c) {
    ull d; asm("fma.rn.f32x2 %0,%1,%2,%3;" : "=l"(d) : "l"(a), "l"(b), "l"(c)); return d;
}
__device__ __forceinline__ void cluster_sync_() {
    asm volatile("barrier.cluster.arrive.aligned;" ::: "memory");
    asm volatile("barrier.cluster.wait.aligned;" ::: "memory");
}

// ---------------- static device scratch (no runtime alloc) ----------------
__device__ float g_xw1[(size_t)64 * 512 * 256];   // xw1[b][t][j]  (32 MB)
__device__ float g_h1[64 * 256];                  // layer-1 hidden state
__device__ float g_h2[64 * 512];                  // layer-2 hidden state

// =====================================================================
// Kernel 1: xw1[b,t,:] = emb[tokens[b,t]] @ W1x + b1
// 1024 blocks x 256 threads; block = 32 flattened (b,t) rows x 256 cols.
// A staged in SMEM as float4[e][m] (m = row-quad), row stride 9 (pad).
// =====================================================================
__global__ void __launch_bounds__(256, 1)
embproj_kernel(const int* __restrict__ tokens, const float* __restrict__ emb,
               const float* __restrict__ W1x, const float* __restrict__ b1)
{
    __shared__ int    t_sm[32];
    __shared__ float4 a_sm[300 * 9];   // slots [e*9 + m], m = 0..7 used

    const int tid  = threadIdx.x;
    const int base = blockIdx.x * 32;  // flattened (b*512+t) tile start

    if (tid < 32) t_sm[tid] = tokens[base + tid];
    __syncthreads();

    // stage A: thread (m4 = tid>>6, e0 = tid&63) fills quads
    {
        const int m4 = tid >> 6;   // 0..3
        const int e0 = tid & 63;
        for (int mm = m4; mm < 8; mm += 4) {
            const int i0 = mm * 4;
            const size_t r0 = (size_t)t_sm[i0 + 0] * 300;
            const size_t r1 = (size_t)t_sm[i0 + 1] * 300;
            const size_t r2 = (size_t)t_sm[i0 + 2] * 300;
            const size_t r3 = (size_t)t_sm[i0 + 3] * 300;
            for (int e = e0; e < 300; e += 64) {
                float4 v;
                v.x = __ldg(emb + r0 + e);
                v.y = __ldg(emb + r1 + e);
                v.z = __ldg(emb + r2 + e);
                v.w = __ldg(emb + r3 + e);
                a_sm[e * 9 + mm] = v;
            }
        }
    }
    __syncthreads();

    const int j = tid;               // output column 0..255
    ull acc[16];
#pragma unroll
    for (int m = 0; m < 16; ++m) acc[m] = 0ull;  // bits 0 == {0.f,0.f}

    const float* wp = W1x + j;
#pragma unroll 2
    for (int e = 0; e < 300; ++e) {
        const ull ws = splat2(__ldg(wp + (size_t)e * 256));
        const ulonglong2* ap = (const ulonglong2*)(a_sm + e * 9);
#pragma unroll
        for (int m2 = 0; m2 < 8; ++m2) {
            ulonglong2 s = ap[m2];             // {rows 4m2,4m2+1},{4m2+2,4m2+3}
            acc[2 * m2]     = fma2(ws, s.x, acc[2 * m2]);
            acc[2 * m2 + 1] = fma2(ws, s.y, acc[2 * m2 + 1]);
        }
    }

    const float bj = __ldg(b1 + j);
#pragma unroll
    for (int m = 0; m < 16; ++m) {
        float2 v = unpack2(acc[m]);
        const size_t row = (size_t)(base + 2 * m);
        g_xw1[row * 256 + j]       = v.x + bj;
        g_xw1[(row + 1) * 256 + j] = v.y + bj;
    }
}

// =====================================================================
// Kernel 2: fused 2-layer recurrence.
// Grid 128 CTAs, clusters of 8. Cluster cl owns batches [4cl, 4cl+4).
// CTA rank r owns layer-1 cols [32r,32r+32), layer-2 cols [64r,64r+64).
// W2x/W2h slice register-resident (96 float2 pairs / thread).
// Superstep t: compute h2(t) = f(h1(t), h2(t-1)) and h1(t+1) = f(h1(t)),
// exchange through L2 (__stcg/__ldcg) with ONE cluster barrier per step.
// =====================================================================
__global__ void __cluster_dims__(8, 1, 1) __launch_bounds__(256, 1)
rnn_kernel(const float* __restrict__ W1h, const float* __restrict__ W2x,
           const float* __restrict__ W2h, const float* __restrict__ b2)
{
    // h staging: hdupAB[k] = {h0,h0,h1,h1}, hdupCD[k] = {h2,h2,h3,h3}
    // (pre-splatted so fma2 needs zero movs); hcomb[k] = {h0,h1,h2,h3}
    // for layer-1 (batch-pair packing). k: 0..255 = h1, 256..767 = h2.
    __shared__ float4 hdupAB[768];
    __shared__ float4 hdupCD[768];
    __shared__ float4 hcomb[256];
    __shared__ float  red2[8 * 32 * 8];   // [g][jp][b*2 + (j&1)]
    __shared__ float  red1[8 * 32 * 4];   // [g][j1][b]
    __shared__ float  b2_s[64];

    const int tid  = threadIdx.x;
    const int rank = blockIdx.x & 7;
    const int b0   = (blockIdx.x >> 3) * 4;
    const int c1   = rank * 32;
    const int c2   = rank * 64;
    const int jp   = tid & 31;   // layer-2 column pair (cols 2jp, 2jp+1)
    const int g    = tid >> 5;   // k-group 0..7 (warp-uniform)
    const int k0   = g * 96;

    // ---- register-resident W2 slice: w[k][c2+2jp .. +1], k in [k0,k0+96) ----
    ull w2r[96];
    {
        const float* x = W2x + c2 + 2 * jp;
        const float* h = W2h + c2 + 2 * jp;
#pragma unroll
        for (int r = 0; r < 96; ++r) {
            const int k = k0 + r;
            const float* p = (k < 256) ? (x + (size_t)k * 512)
                                       : (h + (size_t)(k - 256) * 512);
            w2r[r] = *(const ull*)p;
        }
    }
    if (tid < 64) b2_s[tid] = b2[c2 + tid];

    // ---- init: h1(0) = relu(xw1[:,0,:]),  h2(-1) = 0 ----
    if (tid < 128) {
        const int b = tid >> 5, jj = tid & 31;
        float v = g_xw1[(size_t)((b0 + b) * 512) * 256 + c1 + jj];
        __stcg(&g_h1[(b0 + b) * 256 + c1 + jj], fmaxf(v, 0.f));
    }
    {
        const int b = tid >> 6, jj = tid & 63;
        __stcg(&g_h2[(b0 + b) * 512 + c2 + jj], 0.f);
    }
    cluster_sync_();

    // ---- staging: global (L2) -> SMEM, transposed+duplicated ----
    auto stage = [&]() {
#pragma unroll
        for (int it = 0; it < 3; ++it) {
            const int idx = tid + it * 256;
            float a, bb, c, d;
            if (idx < 256) {
                a  = __ldcg(&g_h1[(b0 + 0) * 256 + idx]);
                bb = __ldcg(&g_h1[(b0 + 1) * 256 + idx]);
                c  = __ldcg(&g_h1[(b0 + 2) * 256 + idx]);
                d  = __ldcg(&g_h1[(b0 + 3) * 256 + idx]);
                hcomb[idx] = make_float4(a, bb, c, d);
            } else {
                const int km = idx - 256;
                a  = __ldcg(&g_h2[(b0 + 0) * 512 + km]);
                bb = __ldcg(&g_h2[(b0 + 1) * 512 + km]);
                c  = __ldcg(&g_h2[(b0 + 2) * 512 + km]);
                d  = __ldcg(&g_h2[(b0 + 3) * 512 + km]);
            }
            hdupAB[idx] = make_float4(a, a, bb, bb);
            hdupCD[idx] = make_float4(c, c, d, d);
        }
    };
    stage();
    __syncthreads();

    const int jf = tid & 63, bf = tid >> 6;   // layer-2 finish mapping

    for (int t = 0; t < 512; ++t) {
        // ---- layer-2 partials (register weights, SMEM h broadcast) ----
        ull a0 = 0, a1 = 0, a2 = 0, a3 = 0;
        {
            const ulonglong2* pAB = ((const ulonglong2*)hdupAB) + k0;
            const ulonglong2* pCD = ((const ulonglong2*)hdupCD) + k0;
#pragma unroll
            for (int r = 0; r < 96; ++r) {
                const ulonglong2 sab = pAB[r];
                const ulonglong2 scd = pCD[r];
                const ull w = w2r[r];
                a0 = fma2(w, sab.x, a0);
                a1 = fma2(w, sab.y, a1);
                a2 = fma2(w, scd.x, a2);
                a3 = fma2(w, scd.y, a3);
            }
        }
        {
            const float2 v0 = unpack2(a0), v1 = unpack2(a1);
            const float2 v2 = unpack2(a2), v3 = unpack2(a3);
            float4* q = (float4*)&red2[(g * 32 + jp) * 8];
            q[0] = make_float4(v0.x, v0.y, v1.x, v1.y);
            q[1] = make_float4(v2.x, v2.y, v3.x, v3.y);
        }

        // ---- layer-1 partials (W1h streamed from L2) ----
        {
            ull p01 = 0, p23 = 0;
            const float* wp = W1h + (size_t)(32 * g) * 256 + c1 + jp;
            const ulonglong2* hp = ((const ulonglong2*)hcomb) + 32 * g;
#pragma unroll
            for (int k = 0; k < 32; ++k) {
                const ull ws = splat2(__ldg(wp + (size_t)k * 256));
                const ulonglong2 s = hp[k];
                p01 = fma2(ws, s.x, p01);
                p23 = fma2(ws, s.y, p23);
            }
            const float2 u = unpack2(p01), v = unpack2(p23);
            *(float4*)&red1[(g * 32 + jp) * 4] = make_float4(u.x, u.y, v.x, v.y);
        }
        __syncthreads();

        // ---- finish layer-2: reduce 8 groups, bias, relu, publish ----
        {
            float s = b2_s[jf];
            const int ridx = (jf >> 1) * 8 + bf * 2 + (jf & 1);
#pragma unroll
            for (int gg = 0; gg < 8; ++gg) s += red2[gg * 256 + ridx];
            __stcg(&g_h2[(b0 + bf) * 512 + c2 + jf], fmaxf(s, 0.f));
        }
        // ---- finish layer-1: reduce, add xw1(t+1), relu, publish ----
        if (t < 511 && tid < 128) {
            const int b = tid >> 5, jj = tid & 31;
            float s = g_xw1[((size_t)((b0 + b) * 512 + (t + 1))) * 256 + c1 + jj];
#pragma unroll
            for (int gg = 0; gg < 8; ++gg) s += red1[gg * 128 + jj * 4 + b];
            __stcg(&g_h1[(b0 + b) * 256 + c1 + jj], fmaxf(s, 0.f));
        }

        cluster_sync_();                 // release stores / acquire peers'
        if (t < 511) {
            stage();
            __syncthreads();
        }
    }
}

// =====================================================================
// Kernel 3: MLP head.  out[b] = sigmoid(relu(relu(h2@Wd1+bd1)@Wd2+bd2)@Wc+bc)
// =====================================================================
__global__ void __launch_bounds__(128, 1)
head_kernel(const float* __restrict__ Wd1, const float* __restrict__ bd1,
            const float* __restrict__ Wd2, const float* __restrict__ bd2,
            const float* __restrict__ Wc,  const float* __restrict__ bc,
            float* __restrict__ out)
{
    __shared__ float h_s[512], d1_s[128], d2_s[64];
    const int b = blockIdx.x, tid = threadIdx.x;

    for (int k = tid; k < 512; k += 128) h_s[k] = g_h2[b * 512 + k];
    __syncthreads();

    {
        float acc = __ldg(bd1 + tid);
#pragma unroll 4
        for (int k = 0; k < 512; ++k)
            acc = fmaf(h_s[k], __ldg(Wd1 + (size_t)k * 128 + tid), acc);
        d1_s[tid] = fmaxf(acc, 0.f);
    }
    __syncthreads();

    if (tid < 64) {
        float acc = __ldg(bd2 + tid);
#pragma unroll 4
        for (int k = 0; k < 128; ++k)
            acc = fmaf(d1_s[k], __ldg(Wd2 + (size_t)k * 64 + tid), acc);
        d2_s[tid] = fmaxf(acc, 0.f);
    }
    __syncthreads();

    if (tid < 32) {
        float p = d2_s[tid] * __ldg(Wc + tid) + d2_s[tid + 32] * __ldg(Wc + tid + 32);
#pragma unroll
        for (int o = 16; o; o >>= 1) p += __shfl_down_sync(0xffffffffu, p, o);
        if (tid == 0) out[b] = 1.f / (1.f + expf(-(p + __ldg(bc))));
    }
}

// =====================================================================
extern "C" void kernel_launch(void* const* d_in, const int* in_sizes, int n_in,
                              void* d_out, int out_size)
{
    const int*   tokens = (const int*)  d_in[0];
    const float* emb    = (const float*)d_in[1];
    const float* W1x    = (const float*)d_in[2];
    const float* W1h    = (const float*)d_in[3];
    const float* b1     = (const float*)d_in[4];
    const float* W2x    = (const float*)d_in[5];
    const float* W2h    = (const float*)d_in[6];
    const float* b2     = (const float*)d_in[7];
    const float* Wd1    = (const float*)d_in[8];
    const float* bd1    = (const float*)d_in[9];
    const float* Wd2    = (const float*)d_in[10];
    const float* bd2    = (const float*)d_in[11];
    const float* Wc     = (const float*)d_in[12];
    const float* bc     = (const float*)d_in[13];
    float* out = (float*)d_out;
    (void)b1; (void)in_sizes; (void)n_in; (void)out_size;

    embproj_kernel<<<1024, 256>>>(tokens, emb, W1x, (const float*)d_in[4]);
    rnn_kernel<<<128, 256>>>(W1h, W2x, W2h, b2);
    head_kernel<<<64, 128>>>(Wd1, bd1, Wd2, bd2, Wc, bc, out);
}